// round 7
// baseline (speedup 1.0000x reference)
#include <cuda_runtime.h>
#include <math.h>

#define T_STEPS 8192
#define HID     1024
#define IN_K    2048
#define NGATE   3072
#define NCTA    128

// ---- device scratch (allocation-free: __device__ globals) ----
__device__ float g_gi[(size_t)T_STEPS * NGATE];      // ~100.7 MB precomputed input gates
__device__ float g_hv[2][HID];                        // double-buffered h
__device__ unsigned g_ctrm[8][32];                    // 8 mirrored step counters, 128B apart

// =====================================================================
// Kernel 1: gi = features @ w_ih[:, :2048]^T + rewards * w_ih[:,2048] + b_ih
// fp32 SIMT GEMM, BM=BN=128, BK=16, 8x8/thread, 2 CTAs/SM.
// Software-pipelined: double-buffered smem; W tile via cp.async, A tile
// register-staged; ONE __syncthreads per k-tile.
// Block (0,0) also resets the scan's mirror counters.
// =====================================================================
#define BM 128
#define BN 128
#define BK 16
#define NTILES (IN_K / BK)

__global__ void __launch_bounds__(256, 2) gi_gemm(
    const float* __restrict__ feat,   // [8192, 2048]
    const float* __restrict__ rew,    // [8192]
    const float* __restrict__ w_ih,   // [3072, 2049]  (row stride 2049!)
    const float* __restrict__ b_ih)   // [3072]
{
    __shared__ float As[2][BK][BM];
    __shared__ float Ws[2][BK][BN];

    const int tid = threadIdx.x;
    if (blockIdx.x == 0 && blockIdx.y == 0 && tid < 8) g_ctrm[tid][0] = 0u;

    const int nBase = blockIdx.x * BN;
    const int mBase = blockIdx.y * BM;
    const int tx = tid & 15;          // n direction
    const int ty = tid >> 4;          // m direction

    // per-thread A-load coords (2 float4 per tile)
    const int arow0 = tid >> 2;              // 0..63
    const int akq0  = (tid & 3) << 2;
    const int arow1 = (tid + 256) >> 2;      // 64..127
    const int akq1  = akq0;

    float acc[8][8];
    #pragma unroll
    for (int i = 0; i < 8; i++)
        #pragma unroll
        for (int j = 0; j < 8; j++) acc[i][j] = 0.f;

    // ---- prologue: stage 0 ----
    float4 a0 = *reinterpret_cast<const float4*>(&feat[(size_t)(mBase + arow0) * IN_K + akq0]);
    float4 a1 = *reinterpret_cast<const float4*>(&feat[(size_t)(mBase + arow1) * IN_K + akq1]);
    #pragma unroll
    for (int v = 0; v < 8; v++) {
        int f   = tid + v * 256;
        int row = f >> 4;
        int kk  = f & 15;
        unsigned dst = (unsigned)__cvta_generic_to_shared(&Ws[0][kk][row]);
        asm volatile("cp.async.ca.shared.global [%0], [%1], 4;"
                     :: "r"(dst), "l"(&w_ih[(size_t)(nBase + row) * 2049 + kk]) : "memory");
    }
    asm volatile("cp.async.commit_group;" ::: "memory");
    As[0][akq0 + 0][arow0] = a0.x; As[0][akq0 + 1][arow0] = a0.y;
    As[0][akq0 + 2][arow0] = a0.z; As[0][akq0 + 3][arow0] = a0.w;
    As[0][akq1 + 0][arow1] = a1.x; As[0][akq1 + 1][arow1] = a1.y;
    As[0][akq1 + 2][arow1] = a1.z; As[0][akq1 + 3][arow1] = a1.w;
    asm volatile("cp.async.wait_group 0;" ::: "memory");
    __syncthreads();

    for (int i = 0; i < NTILES; i++) {
        const int cur = i & 1, nxt = cur ^ 1;
        const int kN = (i + 1) * BK;
        float4 n0, n1;
        if (i + 1 < NTILES) {
            // issue next-tile loads (A -> regs, W -> cp.async), overlap with compute
            n0 = *reinterpret_cast<const float4*>(&feat[(size_t)(mBase + arow0) * IN_K + kN + akq0]);
            n1 = *reinterpret_cast<const float4*>(&feat[(size_t)(mBase + arow1) * IN_K + kN + akq1]);
            #pragma unroll
            for (int v = 0; v < 8; v++) {
                int f   = tid + v * 256;
                int row = f >> 4;
                int kk  = f & 15;
                unsigned dst = (unsigned)__cvta_generic_to_shared(&Ws[nxt][kk][row]);
                asm volatile("cp.async.ca.shared.global [%0], [%1], 4;"
                             :: "r"(dst), "l"(&w_ih[(size_t)(nBase + row) * 2049 + kN + kk]) : "memory");
            }
            asm volatile("cp.async.commit_group;" ::: "memory");
        }

        #pragma unroll
        for (int k = 0; k < BK; k++) {
            float a[8], b[8];
            float4 av0 = *reinterpret_cast<const float4*>(&As[cur][k][ty * 8 + 0]);
            float4 av1 = *reinterpret_cast<const float4*>(&As[cur][k][ty * 8 + 4]);
            float4 bv0 = *reinterpret_cast<const float4*>(&Ws[cur][k][tx * 8 + 0]);
            float4 bv1 = *reinterpret_cast<const float4*>(&Ws[cur][k][tx * 8 + 4]);
            a[0]=av0.x; a[1]=av0.y; a[2]=av0.z; a[3]=av0.w;
            a[4]=av1.x; a[5]=av1.y; a[6]=av1.z; a[7]=av1.w;
            b[0]=bv0.x; b[1]=bv0.y; b[2]=bv0.z; b[3]=bv0.w;
            b[4]=bv1.x; b[5]=bv1.y; b[6]=bv1.z; b[7]=bv1.w;
            #pragma unroll
            for (int ii = 0; ii < 8; ii++)
                #pragma unroll
                for (int jj = 0; jj < 8; jj++)
                    acc[ii][jj] = fmaf(a[ii], b[jj], acc[ii][jj]);
        }

        if (i + 1 < NTILES) {
            As[nxt][akq0 + 0][arow0] = n0.x; As[nxt][akq0 + 1][arow0] = n0.y;
            As[nxt][akq0 + 2][arow0] = n0.z; As[nxt][akq0 + 3][arow0] = n0.w;
            As[nxt][akq1 + 0][arow1] = n1.x; As[nxt][akq1 + 1][arow1] = n1.y;
            As[nxt][akq1 + 2][arow1] = n1.z; As[nxt][akq1 + 3][arow1] = n1.w;
            asm volatile("cp.async.wait_group 0;" ::: "memory");
        }
        __syncthreads();
    }

    // epilogue: + rewards[m]*w_ih[n][2048] + b_ih[n]
    float rw[8], wl[8], bb[8];
    #pragma unroll
    for (int i = 0; i < 8; i++) rw[i] = rew[mBase + ty * 8 + i];
    #pragma unroll
    for (int j = 0; j < 8; j++) {
        int n = nBase + tx * 8 + j;
        wl[j] = w_ih[(size_t)n * 2049 + 2048];
        bb[j] = b_ih[n];
    }
    #pragma unroll
    for (int i = 0; i < 8; i++) {
        int m = mBase + ty * 8 + i;
        #pragma unroll
        for (int j = 0; j < 8; j++) {
            int n = nBase + tx * 8 + j;
            g_gi[(size_t)m * NGATE + n] = acc[i][j] + rw[i] * wl[j] + bb[j];
        }
    }
}

// =====================================================================
// Kernel 2: persistent GRU reverse scan.
// 128 CTAs x 256 threads. CTA c owns units [8c, 8c+8); warp w -> unit u.
// Barrier: thread0 red.release.gpu(+1) on 8 MIRROR words (post syncC);
// warp w acquire-polls mirror[w] directly (no syncA broadcast hop), then
// fetches its h chunk. h double-buffered by parity; safety from counters.
// =====================================================================
__device__ __forceinline__ float sigmoidf_(float x)
{
    return __fdividef(1.f, 1.f + __expf(-x));
}
__device__ __forceinline__ float tanhf_(float x)
{
    float ax = fabsf(x);
    float e  = __expf(-2.f * ax);
    float t  = __fdividef(1.f - e, 1.f + e);
    return copysignf(t, x);
}

__global__ void __launch_bounds__(256, 1) gru_scan(
    const float* __restrict__ w_hh,   // [3072, 1024]
    const float* __restrict__ b_hh,   // [3072]
    float* __restrict__ out)          // [1024]
{
    __shared__ float h_sm[HID];

    const int tid = threadIdx.x;
    const int c = blockIdx.x;
    const int w = tid >> 5;
    const int l = tid & 31;
    const int u = c * 8 + w;

    // ---- register-resident recurrent weights: lane l holds k = l + 32j ----
    float wr[32], wz[32], wn[32];
    {
        const float* pr = w_hh + (size_t)(          u) * HID + l;
        const float* pz = w_hh + (size_t)(HID     + u) * HID + l;
        const float* pn = w_hh + (size_t)(2 * HID + u) * HID + l;
        #pragma unroll
        for (int j = 0; j < 32; j++) {
            wr[j] = pr[32 * j];
            wz[j] = pz[32 * j];
            wn[j] = pn[32 * j];
        }
    }
    const float bhr = b_hh[u];
    const float bhz = b_hh[HID + u];
    const float bhn = b_hh[2 * HID + u];

    // h^0 = 0
    {
        float4 z4 = make_float4(0.f, 0.f, 0.f, 0.f);
        *reinterpret_cast<float4*>(&h_sm[tid * 4]) = z4;
    }
    float hval = 0.f;   // this warp's unit value (h_prev[u])

    unsigned* mymirror = &g_ctrm[w][0];

    for (int s = 0; s < T_STEPS; s++) {
        const int t = T_STEPS - 1 - s;   // reverse scan
        // prefetch gi for this step (independent of h -> issued before poll)
        const float* gip = g_gi + (size_t)t * NGATE + u;
        const float gir = __ldg(gip);
        const float giz = __ldg(gip + HID);
        const float gin = __ldg(gip + 2 * HID);

        if (s > 0) {
            // whole warp polls its own mirror (one coalesced request/iter)
            const unsigned target = (unsigned)s * (unsigned)NCTA;
            unsigned f;
            do {
                asm volatile("ld.acquire.gpu.global.u32 %0, [%1];"
                             : "=r"(f) : "l"(mymirror) : "memory");
            } while (f < target);
            // fetch my h chunk immediately (no CTA broadcast hop)
            float4 hv4;
            asm volatile("ld.global.cg.v4.f32 {%0,%1,%2,%3}, [%4];"
                         : "=f"(hv4.x), "=f"(hv4.y), "=f"(hv4.z), "=f"(hv4.w)
                         : "l"(&g_hv[s & 1][tid * 4]) : "memory");
            *reinterpret_cast<float4*>(&h_sm[tid * 4]) = hv4;
        }
        __syncthreads();   // (B) h staged in smem (all warps)

        // three 1024-dot-products for unit u, split over 32 lanes
        float dr = 0.f, dz = 0.f, dn = 0.f;
        #pragma unroll
        for (int j = 0; j < 32; j++) {
            const float h = h_sm[l + 32 * j];
            dr = fmaf(wr[j], h, dr);
            dz = fmaf(wz[j], h, dz);
            dn = fmaf(wn[j], h, dn);
        }
        #pragma unroll
        for (int o = 16; o > 0; o >>= 1) {
            dr += __shfl_xor_sync(0xffffffffu, dr, o);
            dz += __shfl_xor_sync(0xffffffffu, dz, o);
            dn += __shfl_xor_sync(0xffffffffu, dn, o);
        }

        const float r = sigmoidf_(gir + dr + bhr);
        const float z = sigmoidf_(giz + dz + bhz);
        const float n = tanhf_(gin + r * (dn + bhn));
        hval = (1.f - z) * n + z * hval;

        if (s < T_STEPS - 1) {
            if (l == 0)
                asm volatile("st.global.cg.f32 [%0], %1;"
                             :: "l"(&g_hv[(s + 1) & 1][u]), "f"(hval) : "memory");
            __syncthreads();   // (C) all 8 unit stores done, CTA-ordered before release
            if (tid == 0) {
                #pragma unroll
                for (int m = 0; m < 8; m++)
                    asm volatile("red.release.gpu.global.add.u32 [%0], %1;"
                                 :: "l"(&g_ctrm[m][0]), "r"(1u) : "memory");
            }
        }
    }

    if (l == 0) out[u] = hval;
}

// =====================================================================
extern "C" void kernel_launch(void* const* d_in, const int* in_sizes, int n_in,
                              void* d_out, int out_size)
{
    const float* feat = (const float*)d_in[0];   // [8192, 2048]
    const float* rew  = (const float*)d_in[1];   // [8192]
    const float* w_ih = (const float*)d_in[2];   // [3072, 2049]
    const float* w_hh = (const float*)d_in[3];   // [3072, 1024]
    const float* b_ih = (const float*)d_in[4];   // [3072]
    const float* b_hh = (const float*)d_in[5];   // [3072]
    float* out = (float*)d_out;                  // [1, 1024]

    dim3 ggrid(NGATE / BN, T_STEPS / BM);        // (24, 64)
    gi_gemm<<<ggrid, 256>>>(feat, rew, w_ih, b_ih);
    gru_scan<<<NCTA, 256>>>(w_hh, b_hh, out);
}

// round 8
// speedup vs baseline: 2.3367x; 2.3367x over previous
#include <cuda_runtime.h>
#include <math.h>

#define T_STEPS 8192
#define HID     1024
#define IN_K    2048
#define NGATE   3072
#define SCTA    64            // scan CTAs (barrier participants)

// ---- device scratch (allocation-free: __device__ globals) ----
__device__ float g_gi[(size_t)T_STEPS * NGATE];      // ~100.7 MB precomputed input gates
__device__ float g_hv[2][HID];                        // double-buffered h
__device__ unsigned g_ctr;                            // monotonic step counter (release/acquire, GPU scope)

// =====================================================================
// Kernel 1: gi = features @ w_ih[:, :2048]^T + rewards * w_ih[:,2048] + b_ih
// fp32 SIMT tiled GEMM, BM=BN=128, BK=16, 8x8 per thread, 2 CTAs/SM.
// (R6 version, known good.) Block (0,0) also resets the scan counter.
// =====================================================================
#define BM 128
#define BN 128
#define BK 16

__global__ void __launch_bounds__(256, 2) gi_gemm(
    const float* __restrict__ feat,   // [8192, 2048]
    const float* __restrict__ rew,    // [8192]
    const float* __restrict__ w_ih,   // [3072, 2049]  (row stride 2049!)
    const float* __restrict__ b_ih)   // [3072]
{
    __shared__ float As[BK][BM];
    __shared__ float Ws[BK][BN];

    const int tid   = threadIdx.x;
    if (blockIdx.x == 0 && blockIdx.y == 0 && tid == 0) g_ctr = 0u;

    const int nBase = blockIdx.x * BN;
    const int mBase = blockIdx.y * BM;
    const int tx = tid & 15;          // n direction
    const int ty = tid >> 4;          // m direction

    float acc[8][8];
    #pragma unroll
    for (int i = 0; i < 8; i++)
        #pragma unroll
        for (int j = 0; j < 8; j++) acc[i][j] = 0.f;

    for (int kB = 0; kB < IN_K; kB += BK) {
        #pragma unroll
        for (int v = 0; v < 2; v++) {
            int f   = tid + v * 256;            // 0..511
            int row = f >> 2;
            int kq  = (f & 3) << 2;
            float4 a = *reinterpret_cast<const float4*>(
                &feat[(size_t)(mBase + row) * IN_K + kB + kq]);
            As[kq + 0][row] = a.x;
            As[kq + 1][row] = a.y;
            As[kq + 2][row] = a.z;
            As[kq + 3][row] = a.w;
        }
        #pragma unroll
        for (int v = 0; v < 8; v++) {
            int f   = tid + v * 256;            // 0..2047
            int row = f >> 4;
            int kk  = f & 15;
            Ws[kk][row] = w_ih[(size_t)(nBase + row) * 2049 + kB + kk];
        }
        __syncthreads();

        #pragma unroll
        for (int k = 0; k < BK; k++) {
            float a[8], b[8];
            float4 a0 = *reinterpret_cast<const float4*>(&As[k][ty * 8 + 0]);
            float4 a1 = *reinterpret_cast<const float4*>(&As[k][ty * 8 + 4]);
            float4 b0 = *reinterpret_cast<const float4*>(&Ws[k][tx * 8 + 0]);
            float4 b1 = *reinterpret_cast<const float4*>(&Ws[k][tx * 8 + 4]);
            a[0]=a0.x; a[1]=a0.y; a[2]=a0.z; a[3]=a0.w;
            a[4]=a1.x; a[5]=a1.y; a[6]=a1.z; a[7]=a1.w;
            b[0]=b0.x; b[1]=b0.y; b[2]=b0.z; b[3]=b0.w;
            b[4]=b1.x; b[5]=b1.y; b[6]=b1.z; b[7]=b1.w;
            #pragma unroll
            for (int i = 0; i < 8; i++)
                #pragma unroll
                for (int j = 0; j < 8; j++)
                    acc[i][j] = fmaf(a[i], b[j], acc[i][j]);
        }
        __syncthreads();
    }

    float rw[8], wl[8], bb[8];
    #pragma unroll
    for (int i = 0; i < 8; i++) rw[i] = rew[mBase + ty * 8 + i];
    #pragma unroll
    for (int j = 0; j < 8; j++) {
        int n = nBase + tx * 8 + j;
        wl[j] = w_ih[(size_t)n * 2049 + 2048];
        bb[j] = b_ih[n];
    }
    #pragma unroll
    for (int i = 0; i < 8; i++) {
        int m = mBase + ty * 8 + i;
        #pragma unroll
        for (int j = 0; j < 8; j++) {
            int n = nBase + tx * 8 + j;
            g_gi[(size_t)m * NGATE + n] = acc[i][j] + rw[i] * wl[j] + bb[j];
        }
    }
}

// =====================================================================
// Kernel 2: persistent GRU reverse scan.
// 64 CTAs x 256 threads. CTA c owns units [16c, 16c+16); warp w handles
// the ADJACENT pair u0 = 16c+2w, u1 = u0+1 (192 weight regs/thread).
// Barrier protocol identical to R6 (the proven winner): h st.cg ->
// syncthreads -> thread0 red.release.gpu on ONE counter word; consumer
// thread0 acquire-polls that word, syncthreads, cooperative h fetch.
// Half the arrivals, half the poller streams, smaller arrival spread.
// =====================================================================
__device__ __forceinline__ float sigmoidf_(float x)
{
    return __fdividef(1.f, 1.f + __expf(-x));
}
__device__ __forceinline__ float tanhf_(float x)
{
    float ax = fabsf(x);
    float e  = __expf(-2.f * ax);
    float t  = __fdividef(1.f - e, 1.f + e);
    return copysignf(t, x);
}

__global__ void __launch_bounds__(256, 1) gru_scan(
    const float* __restrict__ w_hh,   // [3072, 1024]
    const float* __restrict__ b_hh,   // [3072]
    float* __restrict__ out)          // [1024]
{
    __shared__ float h_sm[HID];

    const int tid = threadIdx.x;
    const int c = blockIdx.x;
    const int w = tid >> 5;
    const int l = tid & 31;
    const int u0 = c * 16 + 2 * w;    // adjacent unit pair for this warp
    const int u1 = u0 + 1;

    // ---- register-resident recurrent weights for BOTH units ----
    float wr0[32], wz0[32], wn0[32], wr1[32], wz1[32], wn1[32];
    {
        const float* pr0 = w_hh + (size_t)(          u0) * HID + l;
        const float* pz0 = w_hh + (size_t)(HID     + u0) * HID + l;
        const float* pn0 = w_hh + (size_t)(2 * HID + u0) * HID + l;
        #pragma unroll
        for (int j = 0; j < 32; j++) {
            wr0[j] = pr0[32 * j];         wr1[j] = pr0[HID + 32 * j];
            wz0[j] = pz0[32 * j];         wz1[j] = pz0[HID + 32 * j];
            wn0[j] = pn0[32 * j];         wn1[j] = pn0[HID + 32 * j];
        }
    }
    const float2 bhr = *reinterpret_cast<const float2*>(&b_hh[u0]);
    const float2 bhz = *reinterpret_cast<const float2*>(&b_hh[HID + u0]);
    const float2 bhn = *reinterpret_cast<const float2*>(&b_hh[2 * HID + u0]);

    // h^0 = 0
    {
        float4 z4 = make_float4(0.f, 0.f, 0.f, 0.f);
        *reinterpret_cast<float4*>(&h_sm[tid * 4]) = z4;
    }
    float h0 = 0.f, h1 = 0.f;

    unsigned* ctrp = &g_ctr;

    for (int s = 0; s < T_STEPS; s++) {
        const int t = T_STEPS - 1 - s;   // reverse scan
        // prefetch gi for both units (independent of h -> issued before poll)
        const float* gip = g_gi + (size_t)t * NGATE + u0;
        const float2 gir = *reinterpret_cast<const float2*>(gip);
        const float2 giz = *reinterpret_cast<const float2*>(gip + HID);
        const float2 gin = *reinterpret_cast<const float2*>(gip + 2 * HID);

        if (s > 0) {
            if (tid == 0) {
                const unsigned target = (unsigned)s * (unsigned)SCTA;
                unsigned f;
                do {
                    asm volatile("ld.acquire.gpu.global.u32 %0, [%1];"
                                 : "=r"(f) : "l"(ctrp) : "memory");
                } while (f < target);
            }
            __syncthreads();   // (A) barrier observed by all threads
            float4 hv4;
            asm volatile("ld.global.cg.v4.f32 {%0,%1,%2,%3}, [%4];"
                         : "=f"(hv4.x), "=f"(hv4.y), "=f"(hv4.z), "=f"(hv4.w)
                         : "l"(&g_hv[s & 1][tid * 4]) : "memory");
            *reinterpret_cast<float4*>(&h_sm[tid * 4]) = hv4;
        }
        __syncthreads();   // (B) h staged in smem

        // six 1024-dot-products (2 units x 3 gates), h loaded once per j
        float dr0 = 0.f, dz0 = 0.f, dn0 = 0.f;
        float dr1 = 0.f, dz1 = 0.f, dn1 = 0.f;
        #pragma unroll
        for (int j = 0; j < 32; j++) {
            const float h = h_sm[l + 32 * j];
            dr0 = fmaf(wr0[j], h, dr0);  dr1 = fmaf(wr1[j], h, dr1);
            dz0 = fmaf(wz0[j], h, dz0);  dz1 = fmaf(wz1[j], h, dz1);
            dn0 = fmaf(wn0[j], h, dn0);  dn1 = fmaf(wn1[j], h, dn1);
        }
        #pragma unroll
        for (int o = 16; o > 0; o >>= 1) {
            dr0 += __shfl_xor_sync(0xffffffffu, dr0, o);
            dz0 += __shfl_xor_sync(0xffffffffu, dz0, o);
            dn0 += __shfl_xor_sync(0xffffffffu, dn0, o);
            dr1 += __shfl_xor_sync(0xffffffffu, dr1, o);
            dz1 += __shfl_xor_sync(0xffffffffu, dz1, o);
            dn1 += __shfl_xor_sync(0xffffffffu, dn1, o);
        }

        const float r0 = sigmoidf_(gir.x + dr0 + bhr.x);
        const float z0 = sigmoidf_(giz.x + dz0 + bhz.x);
        const float n0 = tanhf_(gin.x + r0 * (dn0 + bhn.x));
        h0 = (1.f - z0) * n0 + z0 * h0;

        const float r1 = sigmoidf_(gir.y + dr1 + bhr.y);
        const float z1 = sigmoidf_(giz.y + dz1 + bhz.y);
        const float n1 = tanhf_(gin.y + r1 * (dn1 + bhn.y));
        h1 = (1.f - z1) * n1 + z1 * h1;

        if (s < T_STEPS - 1) {
            if (l == 0)
                asm volatile("st.global.cg.v2.f32 [%0], {%1,%2};"
                             :: "l"(&g_hv[(s + 1) & 1][u0]), "f"(h0), "f"(h1) : "memory");
            __syncthreads();   // (C) all 16 unit stores issued, CTA-ordered before release
            if (tid == 0)
                asm volatile("red.release.gpu.global.add.u32 [%0], %1;"
                             :: "l"(ctrp), "r"(1u) : "memory");
        }
    }

    if (l == 0) {
        out[u0] = h0;
        out[u1] = h1;
    }
}

// =====================================================================
extern "C" void kernel_launch(void* const* d_in, const int* in_sizes, int n_in,
                              void* d_out, int out_size)
{
    const float* feat = (const float*)d_in[0];   // [8192, 2048]
    const float* rew  = (const float*)d_in[1];   // [8192]
    const float* w_ih = (const float*)d_in[2];   // [3072, 2049]
    const float* w_hh = (const float*)d_in[3];   // [3072, 1024]
    const float* b_ih = (const float*)d_in[4];   // [3072]
    const float* b_hh = (const float*)d_in[5];   // [3072]
    float* out = (float*)d_out;                  // [1, 1024]

    dim3 ggrid(NGATE / BN, T_STEPS / BM);        // (24, 64)
    gi_gemm<<<ggrid, 256>>>(feat, rew, w_ih, b_ih);
    gru_scan<<<SCTA, 256>>>(w_hh, b_hh, out);
}